// round 1
// baseline (speedup 1.0000x reference)
#include <cuda_runtime.h>
#include <math.h>

// Problem constants: preds [8,4,256,256] f32, targets [8,256,256] i32.
#define B 8
#define H 256
#define W 256
#define NCLS 3              // classes 1..3
#define NCB 24              // (cls-1)*8 + b
#define IMG 65536           // H*W
#define NPIX 524288         // B*H*W
#define NT2 12288           // K2 threads = 48 groups * 256 columns

// -------- scratch (__device__ globals; no runtime allocation) --------
__device__ float d_gPos[NCB * IMG];   // squared 1-D row distance to nearest pos
__device__ float d_gNeg[NCB * IMG];   // squared 1-D row distance to nearest neg
__device__ float d_dPos[NCB * IMG];   // final 2-D euclidean distance to pos
__device__ float d_dNeg[NCB * IMG];   // final 2-D euclidean distance to neg
__device__ int           d_fc[256 * NT2];   // fc[q] = g[q] + q*q  (per column)
__device__ int           d_zN[256 * NT2];   // envelope crossing numerators
__device__ unsigned char d_vv[256 * NT2];   // envelope parabola indices
__device__ float d_partial[6 * 2048];       // 3 sums + 3 counts per block

// ---------------------------------------------------------------------
// K1: row pass. Reproduces the reference scan exactly:
//   f[x] = x - x'   (x' = nearest set bit <= x), else 512 + x + 1
//   r[x] = x'' - x  (x'' = nearest set bit >= x), else 512 + (256 - x)
//   g = min(f,r)^2
// ---------------------------------------------------------------------
__device__ __forceinline__ int rowdist(const unsigned* m, int x, bool inv) {
    int w = x >> 5, b = x & 31;
    unsigned mw = inv ? ~m[w] : m[w];
    unsigned u = mw & (0xFFFFFFFFu >> (31 - b));
    int dl;
    if (u) {
        dl = b - (31 - __clz(u));
    } else {
        dl = 512 + x + 1;
        for (int i = w - 1; i >= 0; --i) {
            unsigned vi = inv ? ~m[i] : m[i];
            if (vi) { dl = x - (i * 32 + 31 - __clz(vi)); break; }
        }
    }
    unsigned u2 = mw & (0xFFFFFFFFu << b);
    int dr;
    if (u2) {
        dr = (__ffs(u2) - 1) - b;
    } else {
        dr = 512 + 256 - x;
        for (int i = w + 1; i < 8; ++i) {
            unsigned vi = inv ? ~m[i] : m[i];
            if (vi) { dr = i * 32 + (__ffs(vi) - 1) - x; break; }
        }
    }
    return dl < dr ? dl : dr;
}

__global__ __launch_bounds__(256) void k1_rows(const int* __restrict__ tg) {
    int row = blockIdx.x;              // b*256 + y
    int x = threadIdx.x;
    int tv = tg[row * W + x];
    __shared__ unsigned m[8];
    int lane = x & 31, wi = x >> 5;
    int bb = row >> 8, y = row & 255;
    for (int cls = 1; cls <= NCLS; ++cls) {
        unsigned bal = __ballot_sync(0xFFFFFFFFu, tv == cls);
        if (lane == 0) m[wi] = bal;
        __syncthreads();
        unsigned mp[8];
#pragma unroll
        for (int i = 0; i < 8; ++i) mp[i] = m[i];
        __syncthreads();
        int dp = rowdist(mp, x, false);
        int dn = rowdist(mp, x, true);
        int off = (((cls - 1) * 8 + bb) * 256 + y) * 256 + x;
        d_gPos[off] = (float)(dp * dp);
        d_gNeg[off] = (float)(dn * dn);
    }
}

// ---------------------------------------------------------------------
// K2: exact column EDT via Felzenszwalb lower envelope, one thread per
// (transform, column). All comparisons via integer cross-multiplication
// (|A| <= 654849, denominators <= 510 -> products fit int32), so the
// result equals the exact pointwise min the reference computes.
// ---------------------------------------------------------------------
__global__ __launch_bounds__(64) void k2_edt_cols() {
    int gt = blockIdx.x * 64 + threadIdx.x;   // 0..12287
    int x = gt & 255;
    int g2 = gt >> 8;          // 0..47
    int sel = g2 & 1;
    int cb = g2 >> 1;          // 0..23
    const float* __restrict__ src = sel ? d_gNeg : d_gPos;
    float* __restrict__ dst = sel ? d_dNeg : d_dPos;
    int base = cb * IMG + x;

    // ---- build envelope ----
    int k = 0, vk = 0, vk1 = 0, znk = 0;
    int f0 = (int)src[base];
    int fvk = f0;
    d_fc[gt] = f0;
    d_vv[gt] = 0;
#pragma unroll 1
    for (int q = 1; q < 256; ++q) {
        int fq = (int)src[base + (q << 8)] + q * q;
        d_fc[q * NT2 + gt] = fq;
        int A = fq - fvk;
        int Bd = (q - vk) << 1;
        while (k > 0) {
            int zdk = (vk - vk1) << 1;
            if (A * zdk <= znk * Bd) {  // s <= z[k]  (exact)
                --k;
                vk = vk1;
                fvk = d_fc[vk * NT2 + gt];
                if (k > 0) {
                    vk1 = (int)d_vv[(k - 1) * NT2 + gt];
                    znk = d_zN[k * NT2 + gt];
                }
                A = fq - fvk;
                Bd = (q - vk) << 1;
            } else break;
        }
        ++k;
        vk1 = vk; vk = q; znk = A; fvk = fq;
        d_vv[k * NT2 + gt] = (unsigned char)q;
        d_zN[k * NT2 + gt] = A;
    }

    // ---- evaluate ----
    int j = 0, vj = 0;
    int fvj = f0;
    int vjn = 0, znj1 = 0, zdj1 = 1;
    if (k > 0) {
        vjn = (int)d_vv[NT2 + gt];
        znj1 = d_zN[NT2 + gt];
        zdj1 = (vjn - vj) << 1;
    }
#pragma unroll 1
    for (int y = 0; y < 256; ++y) {
        while (j < k && znj1 < y * zdj1) {   // z[j+1] < y  (exact)
            ++j; vj = vjn;
            fvj = d_fc[vj * NT2 + gt];
            if (j < k) {
                vjn = (int)d_vv[(j + 1) * NT2 + gt];
                znj1 = d_zN[(j + 1) * NT2 + gt];
                zdj1 = (vjn - vj) << 1;
            }
        }
        int dy = y - vj;
        int d2 = dy * dy + (fvj - vj * vj);
        dst[base + (y << 8)] = sqrtf((float)d2);
    }
}

// ---------------------------------------------------------------------
// K3: per-pixel softmax + dmap fuse + block reduction (3 sums, 3 counts)
// ---------------------------------------------------------------------
__global__ __launch_bounds__(256) void k3_reduce(const float* __restrict__ preds,
                                                 const int* __restrict__ tg) {
    int pix = blockIdx.x * 256 + threadIdx.x;
    int bb = pix >> 16;
    int rem = pix & 65535;
    int t = tg[pix];
    const float* p = preds + bb * (4 * IMG) + rem;
    float p0 = p[0], p1 = p[IMG], p2 = p[2 * IMG], p3 = p[3 * IMG];
    float mx = fmaxf(fmaxf(p0, p1), fmaxf(p2, p3));
    float e0 = expf(p0 - mx);
    float e1 = expf(p1 - mx);
    float e2 = expf(p2 - mx);
    float e3 = expf(p3 - mx);
    float inv = 1.0f / (e0 + e1 + e2 + e3);
    float ec[4] = {e0, e1, e2, e3};

    float sv[3], cv[3];
#pragma unroll
    for (int cls = 1; cls <= NCLS; ++cls) {
        int off = ((cls - 1) * 8 + bb) * IMG + rem;
        bool pos = (t == cls);
        float dm = pos ? (1.0f - d_dNeg[off]) : d_dPos[off];
        sv[cls - 1] = dm * ec[cls] * inv;
        cv[cls - 1] = pos ? 1.0f : 0.0f;
    }

    __shared__ float red[256];
    int tid = threadIdx.x;
#pragma unroll
    for (int q = 0; q < 6; ++q) {
        red[tid] = (q < 3) ? sv[q] : cv[q - 3];
        __syncthreads();
        for (int st = 128; st > 0; st >>= 1) {
            if (tid < st) red[tid] += red[tid + st];
            __syncthreads();
        }
        if (tid == 0) d_partial[q * 2048 + blockIdx.x] = red[0];
        __syncthreads();
    }
}

// ---------------------------------------------------------------------
// K4: deterministic final reduction + has/count logic
// ---------------------------------------------------------------------
__global__ __launch_bounds__(256) void k4_final(float* __restrict__ out) {
    __shared__ float red[256];
    __shared__ float tot[6];
    int tid = threadIdx.x;
    for (int q = 0; q < 6; ++q) {
        float s = 0.0f;
        for (int i = tid; i < 2048; i += 256) s += d_partial[q * 2048 + i];
        red[tid] = s;
        __syncthreads();
        for (int st = 128; st > 0; st >>= 1) {
            if (tid < st) red[tid] += red[tid + st];
            __syncthreads();
        }
        if (tid == 0) tot[q] = red[0];
        __syncthreads();
    }
    if (tid == 0) {
        float total = 0.0f, count = 0.0f;
        for (int c = 0; c < 3; ++c) {
            if (tot[3 + c] > 0.0f) {
                total += tot[c] * (1.0f / (float)NPIX);
                count += 1.0f;
            }
        }
        out[0] = (count > 0.0f) ? (total / count) : 0.0f;
    }
}

extern "C" void kernel_launch(void* const* d_in, const int* in_sizes, int n_in,
                              void* d_out, int out_size) {
    const float* preds = (const float*)d_in[0];
    const int* targets = (const int*)d_in[1];
    float* out = (float*)d_out;

    k1_rows<<<B * H, 256>>>(targets);
    k2_edt_cols<<<NT2 / 64, 64>>>();
    k3_reduce<<<NPIX / 256, 256>>>(preds, targets);
    k4_final<<<1, 256>>>(out);
}

// round 2
// speedup vs baseline: 12.4685x; 12.4685x over previous
#include <cuda_runtime.h>
#include <math.h>

// Problem constants: preds [8,4,256,256] f32, targets [8,256,256] i32.
#define B 8
#define H 256
#define W 256
#define NCLS 3              // classes 1..3
#define NCB 24              // cb = (cls-1)*8 + b
#define IMG 65536           // H*W
#define NPIX 524288         // B*H*W
#define RWIN 16             // window radius; exact when result <= RWIN^2

// -------- scratch (__device__ globals; no runtime allocation) --------
__device__ float d_gPos[NCB * IMG];   // squared 1-D row distance to nearest pos
__device__ float d_gNeg[NCB * IMG];   // squared 1-D row distance to nearest neg
__device__ float d_dmap[NCB * IMG];   // fused dmap: pos? 1-dNeg : dPos
__device__ int   d_flag[NCB * W];     // per (cb, x): windowed min not provably exact
__device__ int   d_cnt[NCB * 16];     // per-k2-block pos counts (384 entries)
__device__ float d_partial[3 * 512];  // k3 per-block sums per class

// ---------------------------------------------------------------------
// K1: row pass. Reproduces the reference scan exactly:
//   f[x] = x - x'   (x' = nearest set bit <= x), else 512 + x + 1
//   r[x] = x'' - x  (x'' = nearest set bit >= x), else 512 + (256 - x)
//   g = min(f,r)^2
// ---------------------------------------------------------------------
__device__ __forceinline__ int rowdist(const unsigned* m, int x, bool inv) {
    int w = x >> 5, b = x & 31;
    unsigned mw = inv ? ~m[w] : m[w];
    unsigned u = mw & (0xFFFFFFFFu >> (31 - b));
    int dl;
    if (u) {
        dl = b - (31 - __clz(u));
    } else {
        dl = 512 + x + 1;
        for (int i = w - 1; i >= 0; --i) {
            unsigned vi = inv ? ~m[i] : m[i];
            if (vi) { dl = x - (i * 32 + 31 - __clz(vi)); break; }
        }
    }
    unsigned u2 = mw & (0xFFFFFFFFu << b);
    int dr;
    if (u2) {
        dr = (__ffs(u2) - 1) - b;
    } else {
        dr = 512 + 256 - x;
        for (int i = w + 1; i < 8; ++i) {
            unsigned vi = inv ? ~m[i] : m[i];
            if (vi) { dr = i * 32 + (__ffs(vi) - 1) - x; break; }
        }
    }
    return dl < dr ? dl : dr;
}

__global__ __launch_bounds__(256) void k1_rows(const int* __restrict__ tg) {
    int row = blockIdx.x;              // b*256 + y
    int x = threadIdx.x;
    // clear flags (first 24 blocks)
    if (blockIdx.x < NCB) d_flag[blockIdx.x * W + x] = 0;
    int tv = tg[row * W + x];
    __shared__ unsigned m[8];
    int lane = x & 31, wi = x >> 5;
    int bb = row >> 8, y = row & 255;
    for (int cls = 1; cls <= NCLS; ++cls) {
        unsigned bal = __ballot_sync(0xFFFFFFFFu, tv == cls);
        if (lane == 0) m[wi] = bal;
        __syncthreads();
        unsigned mp[8];
#pragma unroll
        for (int i = 0; i < 8; ++i) mp[i] = m[i];
        __syncthreads();
        int dp = rowdist(mp, x, false);
        int dn = rowdist(mp, x, true);
        int off = (((cls - 1) * 8 + bb) * 256 + y) * 256 + x;
        d_gPos[off] = (float)(dp * dp);
        d_gNeg[off] = (float)(dn * dn);
    }
}

// ---------------------------------------------------------------------
// K2: windowed column EDT (radius 16), fully register-resident & unrolled.
// Exact whenever the windowed min <= 256 (outside candidates >= 289).
// Columns where this can't be certified are flagged for k2_fix.
// Fuses the final dmap (pos <=> gPos==0) and per-class pos counts.
// Grid: 24 cb * 16 y-tiles = 384 blocks of 256 threads (thread = x).
// ---------------------------------------------------------------------
__global__ __launch_bounds__(256) void k2_win() {
    int x = threadIdx.x;
    int cb = blockIdx.x >> 4;
    int y0 = (blockIdx.x & 15) << 4;
    const float* __restrict__ gp = d_gPos + cb * IMG + x;
    const float* __restrict__ gn = d_gNeg + cb * IMG + x;

    float mP[16], mN[16];
    unsigned posbits = 0;
    bool bad = false;

    {   // pos phase
        float v[48];
#pragma unroll
        for (int r = 0; r < 48; ++r) {
            int gy = y0 - RWIN + r;
            v[r] = (gy >= 0 && gy < H) ? gp[gy << 8] : 1e30f;
        }
#pragma unroll
        for (int o = 0; o < 16; ++o) {
            float m = v[o + RWIN];
            if (m == 0.0f) posbits |= (1u << o);
#pragma unroll
            for (int dy = 1; dy <= RWIN; ++dy) {
                float a = (float)(dy * dy);
                m = fminf(m, v[o + RWIN - dy] + a);
                m = fminf(m, v[o + RWIN + dy] + a);
            }
            mP[o] = m;
            if (m > (float)(RWIN * RWIN)) bad = true;
        }
    }
    {   // neg phase
        float v[48];
#pragma unroll
        for (int r = 0; r < 48; ++r) {
            int gy = y0 - RWIN + r;
            v[r] = (gy >= 0 && gy < H) ? gn[gy << 8] : 1e30f;
        }
#pragma unroll
        for (int o = 0; o < 16; ++o) {
            float m = v[o + RWIN];
#pragma unroll
            for (int dy = 1; dy <= RWIN; ++dy) {
                float a = (float)(dy * dy);
                m = fminf(m, v[o + RWIN - dy] + a);
                m = fminf(m, v[o + RWIN + dy] + a);
            }
            mN[o] = m;
            if (m > (float)(RWIN * RWIN)) bad = true;
        }
    }

    if (bad) d_flag[cb * W + x] = 1;   // races benign: all write 1

    float* __restrict__ dm = d_dmap + cb * IMG + x;
#pragma unroll
    for (int o = 0; o < 16; ++o) {
        float val = ((posbits >> o) & 1u) ? (1.0f - sqrtf(mN[o])) : sqrtf(mP[o]);
        dm[(y0 + o) << 8] = val;
    }

    // per-block pos count
    int c = __popc(posbits);
#pragma unroll
    for (int off = 16; off; off >>= 1) c += __shfl_down_sync(0xFFFFFFFFu, c, off);
    __shared__ int sc[8];
    int w = threadIdx.x >> 5;
    if ((threadIdx.x & 31) == 0) sc[w] = c;
    __syncthreads();
    if (threadIdx.x == 0) {
        int t = 0;
#pragma unroll
        for (int i = 0; i < 8; ++i) t += sc[i];
        d_cnt[blockIdx.x] = t;
    }
}

// ---------------------------------------------------------------------
// K2-fix: exact O(H^2) fallback for flagged columns (exactness guarantee
// for arbitrary inputs; never fires on typical masks -> near-zero cost).
// ---------------------------------------------------------------------
__global__ __launch_bounds__(256) void k2_fix() {
    int cb = blockIdx.x;
    int x = threadIdx.x;
    if (!d_flag[cb * W + x]) return;
    const float* __restrict__ gp = d_gPos + cb * IMG + x;
    const float* __restrict__ gn = d_gNeg + cb * IMG + x;
    float* __restrict__ dm = d_dmap + cb * IMG + x;
    for (int y = 0; y < H; ++y) {
        float mp = 1e30f, mn = 1e30f;
        for (int yp = 0; yp < H; ++yp) {
            float dy2 = (float)((y - yp) * (y - yp));
            mp = fminf(mp, gp[yp << 8] + dy2);
            mn = fminf(mn, gn[yp << 8] + dy2);
        }
        bool pos = (gp[y << 8] == 0.0f);
        dm[y << 8] = pos ? (1.0f - sqrtf(mn)) : sqrtf(mp);
    }
}

// ---------------------------------------------------------------------
// K3: softmax + dmap dot, float4-vectorized, shuffle-reduced.
// Grid 512 blocks x 256 threads x 4 pixels.
// ---------------------------------------------------------------------
__global__ __launch_bounds__(256) void k3_red(const float* __restrict__ preds) {
    int t = blockIdx.x * 256 + threadIdx.x;
    int base = t << 2;                // pixel index, multiple of 4
    int bb = base >> 16;
    int rem = base & 65535;
    const float* pb = preds + bb * (4 * IMG) + rem;
    float4 c0 = *(const float4*)(pb);
    float4 c1 = *(const float4*)(pb + IMG);
    float4 c2 = *(const float4*)(pb + 2 * IMG);
    float4 c3 = *(const float4*)(pb + 3 * IMG);
    float4 dm1 = *(const float4*)(d_dmap + (0 * 8 + bb) * IMG + rem);
    float4 dm2 = *(const float4*)(d_dmap + (1 * 8 + bb) * IMG + rem);
    float4 dm3 = *(const float4*)(d_dmap + (2 * 8 + bb) * IMG + rem);

    float a0[4] = {c0.x, c0.y, c0.z, c0.w};
    float a1[4] = {c1.x, c1.y, c1.z, c1.w};
    float a2[4] = {c2.x, c2.y, c2.z, c2.w};
    float a3[4] = {c3.x, c3.y, c3.z, c3.w};
    float g1[4] = {dm1.x, dm1.y, dm1.z, dm1.w};
    float g2[4] = {dm2.x, dm2.y, dm2.z, dm2.w};
    float g3[4] = {dm3.x, dm3.y, dm3.z, dm3.w};

    float s0 = 0.0f, s1 = 0.0f, s2 = 0.0f;
#pragma unroll
    for (int e = 0; e < 4; ++e) {
        float mx = fmaxf(fmaxf(a0[e], a1[e]), fmaxf(a2[e], a3[e]));
        float e0 = expf(a0[e] - mx);
        float e1 = expf(a1[e] - mx);
        float e2 = expf(a2[e] - mx);
        float e3 = expf(a3[e] - mx);
        float inv = 1.0f / (e0 + e1 + e2 + e3);
        s0 += g1[e] * e1 * inv;
        s1 += g2[e] * e2 * inv;
        s2 += g3[e] * e3 * inv;
    }

#pragma unroll
    for (int off = 16; off; off >>= 1) {
        s0 += __shfl_down_sync(0xFFFFFFFFu, s0, off);
        s1 += __shfl_down_sync(0xFFFFFFFFu, s1, off);
        s2 += __shfl_down_sync(0xFFFFFFFFu, s2, off);
    }
    __shared__ float sm[8][3];
    int w = threadIdx.x >> 5;
    if ((threadIdx.x & 31) == 0) { sm[w][0] = s0; sm[w][1] = s1; sm[w][2] = s2; }
    __syncthreads();
    if (threadIdx.x < 3) {
        float tt = 0.0f;
#pragma unroll
        for (int i = 0; i < 8; ++i) tt += sm[i][threadIdx.x];
        d_partial[threadIdx.x * 512 + blockIdx.x] = tt;
    }
}

// ---------------------------------------------------------------------
// K4: final deterministic reduction + has/count logic.
// ---------------------------------------------------------------------
__global__ __launch_bounds__(256) void k4_final(float* __restrict__ out) {
    __shared__ float red[256];
    __shared__ float tot[3];
    __shared__ float cls_cnt[3];
    int tid = threadIdx.x;
    for (int q = 0; q < 3; ++q) {
        float s = d_partial[q * 512 + tid] + d_partial[q * 512 + 256 + tid];
        red[tid] = s;
        __syncthreads();
        for (int st = 128; st; st >>= 1) {
            if (tid < st) red[tid] += red[tid + st];
            __syncthreads();
        }
        if (tid == 0) tot[q] = red[0];
        __syncthreads();
    }
    for (int q = 0; q < 3; ++q) {
        red[tid] = (tid < 128) ? (float)d_cnt[q * 128 + tid] : 0.0f;
        __syncthreads();
        for (int st = 128; st; st >>= 1) {
            if (tid < st) red[tid] += red[tid + st];
            __syncthreads();
        }
        if (tid == 0) cls_cnt[q] = red[0];
        __syncthreads();
    }
    if (tid == 0) {
        float total = 0.0f, count = 0.0f;
        for (int c = 0; c < 3; ++c) {
            if (cls_cnt[c] > 0.0f) {
                total += tot[c] * (1.0f / (float)NPIX);
                count += 1.0f;
            }
        }
        out[0] = (count > 0.0f) ? (total / count) : 0.0f;
    }
}

extern "C" void kernel_launch(void* const* d_in, const int* in_sizes, int n_in,
                              void* d_out, int out_size) {
    const float* preds = (const float*)d_in[0];
    const int* targets = (const int*)d_in[1];
    float* out = (float*)d_out;

    k1_rows<<<B * H, 256>>>(targets);
    k2_win<<<NCB * 16, 256>>>();
    k2_fix<<<NCB, 256>>>();
    k3_red<<<NPIX / 1024, 256>>>(preds);
    k4_final<<<1, 256>>>(out);
}